// round 13
// baseline (speedup 1.0000x reference)
#include <cuda_runtime.h>
#include <cuda_bf16.h>
#include <cstdint>

// ---------------------------------------------------------------------------
// GATv2 layer — edge phase factored by DATA:
//   K0 prep_kernel : zero histogram; split X + weights into hi/lo bf16
//   K1 gemm_async<256,true> : [L|R] bf16 + V fp32 = X @ [Wl|Wr|Wv] + bias
//   K2 hist/scan/scatter : CSR binning of edges by target
//   K3 ebias_kernel (EDGE order): edge_bias[e][h] = ef[e]@We[:,h] + be[h]
//        -> the ONLY consumer of the 204MB ef stream, fully coalesced
//   K4 agg_kernel  (BIN order, atomic-free): warp-per-node; L[t] loaded ONCE,
//        per edge gathers only R[s]+V[s]+edge_bias; score+exp+accumulate in
//        registers; normalize + bf16-split write in epilogue
//   K5 gemm_async<128,false> : out = norm_agg @ Wo + bo
// ---------------------------------------------------------------------------

#define N_MAX 50048
#define E_MAX 800256
#define IN_F  256

// CSR structures
__device__ int g_cnt[N_MAX];
__device__ int g_off[N_MAX + 1];
__device__ int g_cur[N_MAX];
__device__ int g_bin[E_MAX];

// per-edge bias scores (pre-exp): ef@We + be
__device__ __align__(16) float g_ebias[(size_t)E_MAX * 8];

// edge-pass operands (written by proj GEMM epilogue)
__device__ __align__(16) __nv_bfloat16 g_edgeLR[(size_t)N_MAX * 256]; // [n][L|R]
__device__ __align__(16) float         g_valf  [(size_t)N_MAX * 128]; // V fp32

// bf16-split GEMM operands
__device__ __align__(16) __nv_bfloat16 g_Xhi[(size_t)N_MAX * 256];
__device__ __align__(16) __nv_bfloat16 g_Xlo[(size_t)N_MAX * 256];
__device__ __align__(16) __nv_bfloat16 g_Ahi_o[(size_t)N_MAX * 128];
__device__ __align__(16) __nv_bfloat16 g_Alo_o[(size_t)N_MAX * 128];
// transposed weights [band][n][k] (B[n][k] = W[k][n])
__device__ __align__(16) __nv_bfloat16 g_Bhi_p[3 * 128 * 256];
__device__ __align__(16) __nv_bfloat16 g_Blo_p[3 * 128 * 256];
__device__ __align__(16) __nv_bfloat16 g_Bhi_o[128 * 128];
__device__ __align__(16) __nv_bfloat16 g_Blo_o[128 * 128];
__device__ __align__(16) float g_bias_p[384];

// ------------------------------ helpers ------------------------------------
__device__ __forceinline__ uint32_t s2u(const void* p) {
    uint32_t a;
    asm("{ .reg .u64 t; cvta.to.shared.u64 t, %1; cvt.u32.u64 %0, t; }"
        : "=r"(a) : "l"(p));
    return a;
}

__device__ __forceinline__ void cpa16(uint32_t dst, const void* src) {
    asm volatile("cp.async.cg.shared.global [%0], [%1], 16;"
                 :: "r"(dst), "l"(src));
}

__device__ __forceinline__ void ldmA(uint32_t* a, uint32_t addr) {
    asm volatile("ldmatrix.sync.aligned.m8n8.x4.shared.b16 {%0,%1,%2,%3}, [%4];"
                 : "=r"(a[0]), "=r"(a[1]), "=r"(a[2]), "=r"(a[3]) : "r"(addr));
}

__device__ __forceinline__ void mma16816(float* c, const uint32_t* a,
                                         uint32_t b0, uint32_t b1) {
    asm volatile(
        "mma.sync.aligned.m16n8k16.row.col.f32.bf16.bf16.f32 "
        "{%0,%1,%2,%3},{%4,%5,%6,%7},{%8,%9},{%0,%1,%2,%3};"
        : "+f"(c[0]), "+f"(c[1]), "+f"(c[2]), "+f"(c[3])
        : "r"(a[0]), "r"(a[1]), "r"(a[2]), "r"(a[3]), "r"(b0), "r"(b1));
}

__device__ __forceinline__ float4 ldg_stream4(const float4* p) {
    return __ldcs(p);
}

// pack 2 floats -> hi bf16x2 (returned) + lo bf16x2 (out param)
__device__ __forceinline__ uint32_t pack2(float x, float y, uint32_t& lo) {
    __nv_bfloat16 hx = __float2bfloat16_rn(x);
    __nv_bfloat16 hy = __float2bfloat16_rn(y);
    __nv_bfloat16 lx = __float2bfloat16_rn(x - __bfloat162float(hx));
    __nv_bfloat16 ly = __float2bfloat16_rn(y - __bfloat162float(hy));
    lo = (uint32_t)__bfloat16_as_ushort(lx) | ((uint32_t)__bfloat16_as_ushort(ly) << 16);
    return (uint32_t)__bfloat16_as_ushort(hx) | ((uint32_t)__bfloat16_as_ushort(hy) << 16);
}

// ------------------------------- K0: prep ----------------------------------
__global__ void __launch_bounds__(256) prep_kernel(
    const float* __restrict__ X,
    const float* __restrict__ Wl, const float* __restrict__ bl,
    const float* __restrict__ Wr, const float* __restrict__ br,
    const float* __restrict__ Wv, const float* __restrict__ bv,
    const float* __restrict__ Wo, int n_nodes)
{
    int idx0 = blockIdx.x * blockDim.x + threadIdx.x;
    int stride = gridDim.x * blockDim.x;

    for (int i = idx0; i < n_nodes; i += stride)
        g_cnt[i] = 0;

    int nX2 = n_nodes * 128;     // float pairs
    for (int i = idx0; i < nX2; i += stride) {
        float2 v = reinterpret_cast<const float2*>(X)[i];
        uint32_t lo;
        uint32_t hi = pack2(v.x, v.y, lo);
        reinterpret_cast<uint32_t*>(g_Xhi)[i] = hi;
        reinterpret_cast<uint32_t*>(g_Xlo)[i] = lo;
    }

    for (int i = idx0; i < 3 * 128 * 256; i += stride) {
        int band = i >> 15;
        int n = (i >> 8) & 127;
        int k = i & 255;
        const float* W = band == 0 ? Wl : (band == 1 ? Wr : Wv);
        float v = W[k * 128 + n];
        __nv_bfloat16 h = __float2bfloat16_rn(v);
        g_Bhi_p[i] = h;
        g_Blo_p[i] = __float2bfloat16_rn(v - __bfloat162float(h));
    }
    for (int i = idx0; i < 128 * 128; i += stride) {
        int n = i >> 7, k = i & 127;
        float v = Wo[k * 128 + n];
        __nv_bfloat16 h = __float2bfloat16_rn(v);
        g_Bhi_o[i] = h;
        g_Blo_o[i] = __float2bfloat16_rn(v - __bfloat162float(h));
    }
    for (int i = idx0; i < 384; i += stride)
        g_bias_p[i] = i < 128 ? bl[i] : (i < 256 ? br[i - 128] : bv[i - 256]);
}

// ---------------- K1/K5: cp.async 2-stage split-bf16 MMA GEMM --------------
static constexpr int TSTRIDE = 40;
static constexpr int TILE_B  = 128 * TSTRIDE * 2;  // 10240 B
static constexpr int STAGE_B = 4 * TILE_B;         // 40960 B
static constexpr int GEMM_SMEM = 2 * STAGE_B;      // 81920 B

template<int KT, bool PROJ>
__global__ void __launch_bounds__(256, 2) gemm_async(
    const float* __restrict__ bias_ext, float* __restrict__ out_ext, int M)
{
    constexpr int NCH = KT / 32;
    extern __shared__ char smem[];
    const uint32_t sb = s2u(smem);

    const int tid  = threadIdx.x;
    const int wid  = tid >> 5;
    const int lane = tid & 31;
    const int band = blockIdx.y;
    const int rowBase = blockIdx.x * 128;
    const int warpM = (wid & 3) * 32;
    const int warpN = (wid >> 2) * 64;
    const int g  = lane >> 2;
    const int tg = lane & 3;

    const __nv_bfloat16* Ah = PROJ ? g_Xhi : g_Ahi_o;
    const __nv_bfloat16* Al = PROJ ? g_Xlo : g_Alo_o;
    const __nv_bfloat16* Bh = PROJ ? (g_Bhi_p + (size_t)band * 128 * 256) : g_Bhi_o;
    const __nv_bfloat16* Bl = PROJ ? (g_Blo_p + (size_t)band * 128 * 256) : g_Blo_o;

    const int r0c  = tid >> 2;
    const int g2c  = tid & 3;
    const uint32_t dst0 = sb + (uint32_t)(r0c * 80 + g2c * 16);
    const size_t aoff0 = ((size_t)(rowBase + r0c) * KT) * 2 + g2c * 16;
    const size_t boff0 = ((size_t)r0c * KT) * 2 + g2c * 16;

    float acc[2][8][4];
#pragma unroll
    for (int mt = 0; mt < 2; mt++)
#pragma unroll
        for (int nt = 0; nt < 8; nt++)
#pragma unroll
            for (int j = 0; j < 4; j++) acc[mt][nt][j] = 0.f;

    const uint32_t ldmOff =
        (uint32_t)(((warpM + (lane & 7) + (lane & 8)) * TSTRIDE + ((lane >> 4) << 3)) * 2);
    const uint32_t bBase = (uint32_t)((warpN + g) * (TSTRIDE / 2) + tg);

    auto issue = [&](int c, int s) {
        const size_t kb = (size_t)(c * 32) * 2;
        const uint32_t so = (uint32_t)(s * STAGE_B);
#pragma unroll
        for (int i = 0; i < 2; i++) {
            const uint32_t d = dst0 + so + (uint32_t)(i * 64 * 80);
            const size_t ao = aoff0 + kb + (size_t)i * 64 * KT * 2;
            const size_t bo = boff0 + kb + (size_t)i * 64 * KT * 2;
            cpa16(d,              (const char*)Ah + ao);
            cpa16(d + TILE_B,     (const char*)Al + ao);
            cpa16(d + 2 * TILE_B, (const char*)Bh + bo);
            cpa16(d + 3 * TILE_B, (const char*)Bl + bo);
        }
        asm volatile("cp.async.commit_group;");
    };

    issue(0, 0);
#pragma unroll
    for (int c = 0; c < NCH; c++) {
        if (c + 1 < NCH) {
            issue(c + 1, (c + 1) & 1);
            asm volatile("cp.async.wait_group 1;");
        } else {
            asm volatile("cp.async.wait_group 0;");
        }
        __syncthreads();

        const uint32_t so = (uint32_t)((c & 1) * STAGE_B);
        const uint32_t sAhi = sb + so;
        const uint32_t sAlo = sAhi + TILE_B;
        const uint32_t* BHu = reinterpret_cast<const uint32_t*>(smem + (c & 1) * STAGE_B + 2 * TILE_B);
        const uint32_t* BLu = reinterpret_cast<const uint32_t*>(smem + (c & 1) * STAGE_B + 3 * TILE_B);

#pragma unroll
        for (int k16 = 0; k16 < 2; k16++) {
            uint32_t ah[2][4], al[2][4];
            uint32_t ko = ldmOff + (uint32_t)(k16 * 32);
            ldmA(ah[0], sAhi + ko);
            ldmA(ah[1], sAhi + ko + (uint32_t)(16 * TSTRIDE * 2));
            ldmA(al[0], sAlo + ko);
            ldmA(al[1], sAlo + ko + (uint32_t)(16 * TSTRIDE * 2));
#pragma unroll
            for (int nt = 0; nt < 8; nt++) {
                uint32_t idx = bBase + (uint32_t)(nt * 8 * (TSTRIDE / 2) + k16 * 8);
                uint32_t bh0 = BHu[idx], bh1 = BHu[idx + 4];
                uint32_t bl0 = BLu[idx], bl1 = BLu[idx + 4];
                mma16816(acc[0][nt], ah[0], bh0, bh1);
                mma16816(acc[1][nt], ah[1], bh0, bh1);
                mma16816(acc[0][nt], ah[0], bl0, bl1);
                mma16816(acc[1][nt], ah[1], bl0, bl1);
                mma16816(acc[0][nt], al[0], bh0, bh1);
                mma16816(acc[1][nt], al[1], bh0, bh1);
            }
        }
        __syncthreads();
    }

    // ---- epilogue ----
    if (PROJ) {
        if (band == 2) {
            // V -> fp32 (precision-critical after softmax shrinkage)
#pragma unroll
            for (int mt = 0; mt < 2; mt++) {
                int r0 = rowBase + warpM + mt * 16 + g;
#pragma unroll
                for (int nt = 0; nt < 8; nt++) {
                    int col = warpN + nt * 8 + tg * 2;
                    float b0 = g_bias_p[256 + col], b1 = g_bias_p[256 + col + 1];
                    if (r0 < M) {
                        float2 v = make_float2(acc[mt][nt][0] + b0, acc[mt][nt][1] + b1);
                        *reinterpret_cast<float2*>(g_valf + (size_t)r0 * 128 + col) = v;
                    }
                    if (r0 + 8 < M) {
                        float2 v = make_float2(acc[mt][nt][2] + b0, acc[mt][nt][3] + b1);
                        *reinterpret_cast<float2*>(g_valf + (size_t)(r0 + 8) * 128 + col) = v;
                    }
                }
            }
        } else {
            // L/R -> bf16 (score path, abs err ~8e-5)
#pragma unroll
            for (int mt = 0; mt < 2; mt++) {
                int r0 = rowBase + warpM + mt * 16 + g;
#pragma unroll
                for (int nt = 0; nt < 8; nt++) {
                    int col = warpN + nt * 8 + tg * 2;
                    float b0 = g_bias_p[band * 128 + col];
                    float b1 = g_bias_p[band * 128 + col + 1];
                    if (r0 < M) {
                        __nv_bfloat162 h = __floats2bfloat162_rn(acc[mt][nt][0] + b0,
                                                                 acc[mt][nt][1] + b1);
                        *reinterpret_cast<__nv_bfloat162*>(
                            g_edgeLR + (size_t)r0 * 256 + band * 128 + col) = h;
                    }
                    if (r0 + 8 < M) {
                        __nv_bfloat162 h = __floats2bfloat162_rn(acc[mt][nt][2] + b0,
                                                                 acc[mt][nt][3] + b1);
                        *reinterpret_cast<__nv_bfloat162*>(
                            g_edgeLR + (size_t)(r0 + 8) * 256 + band * 128 + col) = h;
                    }
                }
            }
        }
    } else {
#pragma unroll
        for (int mt = 0; mt < 2; mt++) {
            int r0 = rowBase + warpM + mt * 16 + g;
#pragma unroll
            for (int nt = 0; nt < 8; nt++) {
                int col = warpN + nt * 8 + tg * 2;
                float b0 = bias_ext[col], b1 = bias_ext[col + 1];
                if (r0 < M) {
                    float2 v = make_float2(acc[mt][nt][0] + b0, acc[mt][nt][1] + b1);
                    *reinterpret_cast<float2*>(out_ext + (size_t)r0 * 128 + col) = v;
                }
                if (r0 + 8 < M) {
                    float2 v = make_float2(acc[mt][nt][2] + b0, acc[mt][nt][3] + b1);
                    *reinterpret_cast<float2*>(out_ext + (size_t)(r0 + 8) * 128 + col) = v;
                }
            }
        }
    }
}

// --------------------------- CSR build -------------------------------------
__global__ void __launch_bounds__(256) hist_kernel(const int* __restrict__ ei, int E) {
    int i = blockIdx.x * blockDim.x + threadIdx.x;
    int stride = gridDim.x * blockDim.x;
    for (int e = i; e < E; e += stride)
        atomicAdd(&g_cnt[__ldg(ei + E + e)], 1);
}

__global__ void __launch_bounds__(1024) scan_kernel(int n_nodes) {
    __shared__ int wsum[32];
    __shared__ int s_carry;
    int tid = threadIdx.x, lane = tid & 31, wid = tid >> 5;
    if (tid == 0) s_carry = 0;
    __syncthreads();
    int nChunks = (n_nodes + 1023) >> 10;
    for (int c = 0; c < nChunks; c++) {
        int i = (c << 10) + tid;
        int v = (i < n_nodes) ? g_cnt[i] : 0;
        int x = v;
#pragma unroll
        for (int o = 1; o < 32; o <<= 1) {
            int y = __shfl_up_sync(0xffffffffu, x, o);
            if (lane >= o) x += y;
        }
        if (lane == 31) wsum[wid] = x;
        __syncthreads();
        if (wid == 0) {
            int w = wsum[lane];
#pragma unroll
            for (int o = 1; o < 32; o <<= 1) {
                int y = __shfl_up_sync(0xffffffffu, w, o);
                if (lane >= o) w += y;
            }
            wsum[lane] = w;
        }
        __syncthreads();
        int base = s_carry + (wid > 0 ? wsum[wid - 1] : 0);
        int excl = base + x - v;
        if (i < n_nodes) { g_off[i] = excl; g_cur[i] = excl; }
        __syncthreads();
        if (tid == 1023) s_carry = base + x;
        __syncthreads();
    }
    if (tid == 0) g_off[n_nodes] = s_carry;
}

__global__ void __launch_bounds__(256) scatter_kernel(const int* __restrict__ ei, int E) {
    int i = blockIdx.x * blockDim.x + threadIdx.x;
    int stride = gridDim.x * blockDim.x;
    for (int e = i; e < E; e += stride) {
        int t = __ldg(ei + E + e);
        int pos = atomicAdd(&g_cur[t], 1);
        g_bin[pos] = e;
    }
}

// ------------- K3: edge-bias pass (EDGE order, pure stream) ----------------
// Warp per edge. The ONLY consumer of ef: fully coalesced forward stream.
// Stores ef@We + be (pre-exp) per (edge, head).
__global__ void __launch_bounds__(256) ebias_kernel(
    const float* __restrict__ ef, const float* __restrict__ We,
    const float* __restrict__ be, int E)
{
    const int tid   = threadIdx.x;
    const int lane  = tid & 31;
    const int h     = lane >> 2;
    const int chunk = lane & 3;

    float beh = be[h];
    float w[16];
#pragma unroll
    for (int j = 0; j < 16; j++)
        w[j] = We[(chunk * 16 + j) * 8 + h];

    int gw = (blockIdx.x * 256 + tid) >> 5;
    int nw = (gridDim.x * 256) >> 5;

    for (int e = gw; e < E; e += nw) {
        const float4* pe = reinterpret_cast<const float4*>(ef + (size_t)e * 64 + chunk * 16);
        float4 e0 = ldg_stream4(pe + 0);
        float4 e1 = ldg_stream4(pe + 1);
        float4 e2 = ldg_stream4(pe + 2);
        float4 e3 = ldg_stream4(pe + 3);

        float p = 0.f;
        p = fmaf(e0.x, w[0],  p); p = fmaf(e0.y, w[1],  p);
        p = fmaf(e0.z, w[2],  p); p = fmaf(e0.w, w[3],  p);
        p = fmaf(e1.x, w[4],  p); p = fmaf(e1.y, w[5],  p);
        p = fmaf(e1.z, w[6],  p); p = fmaf(e1.w, w[7],  p);
        p = fmaf(e2.x, w[8],  p); p = fmaf(e2.y, w[9],  p);
        p = fmaf(e2.z, w[10], p); p = fmaf(e2.w, w[11], p);
        p = fmaf(e3.x, w[12], p); p = fmaf(e3.y, w[13], p);
        p = fmaf(e3.z, w[14], p); p = fmaf(e3.w, w[15], p);

        p += __shfl_xor_sync(0xffffffffu, p, 1);
        p += __shfl_xor_sync(0xffffffffu, p, 2);

        if (chunk == 0)
            g_ebias[(size_t)e * 8 + h] = p + beh;
    }
}

// -------- K4: fused score+aggregate (BIN order, atomic-free) ---------------
// Warp owns node t: L[t] loaded ONCE (kills the 204MB per-edge L gather).
// Per edge: R[s] bf16 + V[s] fp32 + edge_bias — all L2-resident. Score, exp,
// and weighted accumulation entirely in registers; normalize + bf16-split
// write in epilogue.
__global__ void __launch_bounds__(256) agg_kernel(
    const int* __restrict__ ei, const float* __restrict__ av,
    int n_nodes, int E)
{
    const int tid  = threadIdx.x;
    const int lane = tid & 31;
    const int h    = lane >> 2;
    const int i0   = lane << 2;
    const int t    = (blockIdx.x * 256 + tid) >> 5;
    if (t >= n_nodes) return;   // warp-uniform

    float4 A4 = *reinterpret_cast<const float4*>(av + i0);

    const __nv_bfloat162* Lp =
        reinterpret_cast<const __nv_bfloat162*>(g_edgeLR + (size_t)t * 256 + i0);
    float2 L01 = __bfloat1622float2(Lp[0]);
    float2 L23 = __bfloat1622float2(Lp[1]);

    int j0 = __ldg(g_off + t), j1 = __ldg(g_off + t + 1);

    float accS = 0.f;
    float4 accV = make_float4(0.f, 0.f, 0.f, 0.f);

    int e = 0, s = 0;
    if (j0 < j1) { e = __ldg(g_bin + j0); s = __ldg(ei + e); }

    for (int j = j0; j < j1; j++) {
        int ec = e, sc = s;
        if (j + 1 < j1) { e = __ldg(g_bin + j + 1); s = __ldg(ei + e); }

        const __nv_bfloat162* Rp =
            reinterpret_cast<const __nv_bfloat162*>(g_edgeLR + (size_t)sc * 256 + 128 + i0);
        __nv_bfloat162 Rb0 = Rp[0], Rb1 = Rp[1];
        float4 V = *reinterpret_cast<const float4*>(g_valf + (size_t)sc * 128 + i0);
        float bias_e = __ldg(g_ebias + (size_t)ec * 8 + h);

        float2 R01 = __bfloat1622float2(Rb0), R23 = __bfloat1622float2(Rb1);

        float cx = L01.x + R01.x; cx = cx > 0.f ? cx : 0.2f * cx;
        float cy = L01.y + R01.y; cy = cy > 0.f ? cy : 0.2f * cy;
        float cz = L23.x + R23.x; cz = cz > 0.f ? cz : 0.2f * cz;
        float cw = L23.y + R23.y; cw = cw > 0.f ? cw : 0.2f * cw;
        float p = cx * A4.x + cy * A4.y + cz * A4.z + cw * A4.w;

        p += __shfl_xor_sync(0xffffffffu, p, 1);
        p += __shfl_xor_sync(0xffffffffu, p, 2);

        float ex = __expf(p + bias_e);
        accS += ex;
        accV.x = fmaf(ex, V.x, accV.x);
        accV.y = fmaf(ex, V.y, accV.y);
        accV.z = fmaf(ex, V.z, accV.z);
        accV.w = fmaf(ex, V.w, accV.w);
    }

    float inv = 1.f / (accS + 1e-10f);
    uint2 hi, lo;
    hi.x = pack2(accV.x * inv, accV.y * inv, lo.x);
    hi.y = pack2(accV.z * inv, accV.w * inv, lo.y);
    *reinterpret_cast<uint2*>(
        reinterpret_cast<char*>(g_Ahi_o) + (size_t)t * 256 + lane * 8) = hi;
    *reinterpret_cast<uint2*>(
        reinterpret_cast<char*>(g_Alo_o) + (size_t)t * 256 + lane * 8) = lo;
}

// ------------------------------- launcher ----------------------------------
extern "C" void kernel_launch(void* const* d_in, const int* in_sizes, int n_in,
                              void* d_out, int out_size)
{
    const float* X  = (const float*)d_in[0];
    const int*   ei = (const int*)  d_in[1];
    const float* ef = (const float*)d_in[2];
    const float* Wl = (const float*)d_in[3];
    const float* bl = (const float*)d_in[4];
    const float* Wr = (const float*)d_in[5];
    const float* br = (const float*)d_in[6];
    const float* We = (const float*)d_in[7];
    const float* be = (const float*)d_in[8];
    const float* av = (const float*)d_in[9];
    const float* Wv = (const float*)d_in[10];
    const float* bv = (const float*)d_in[11];
    const float* Wo = (const float*)d_in[12];
    const float* bo = (const float*)d_in[13];

    int n_nodes = in_sizes[0] / IN_F;
    int E       = in_sizes[1] / 2;
    float* out  = (float*)d_out;
    int nBlocks = (n_nodes + 127) / 128;

    cudaFuncSetAttribute(gemm_async<256, true>,
                         cudaFuncAttributeMaxDynamicSharedMemorySize, GEMM_SMEM);
    cudaFuncSetAttribute(gemm_async<128, false>,
                         cudaFuncAttributeMaxDynamicSharedMemorySize, GEMM_SMEM);

    prep_kernel<<<2048, 256>>>(X, Wl, bl, Wr, br, Wv, bv, Wo, n_nodes);

    hist_kernel<<<1024, 256>>>(ei, E);
    scan_kernel<<<1, 1024>>>(n_nodes);
    scatter_kernel<<<1024, 256>>>(ei, E);

    // ebias: pure ef stream, independent of GEMM -> run before proj so its
    // DRAM traffic overlaps nothing tensor-bound
    ebias_kernel<<<8192, 256>>>(ef, We, be, E);

    dim3 g1(nBlocks, 3);
    gemm_async<256, true><<<g1, 256, GEMM_SMEM>>>(nullptr, nullptr, n_nodes);

    agg_kernel<<<(n_nodes * 32 + 255) / 256, 256>>>(ei, av, n_nodes, E);

    gemm_async<128, false><<<dim3(nBlocks, 1), 256, GEMM_SMEM>>>(bo, out, n_nodes);
}

// round 14
// speedup vs baseline: 1.0628x; 1.0628x over previous
#include <cuda_runtime.h>
#include <cuda_bf16.h>
#include <cstdint>

// ---------------------------------------------------------------------------
// GATv2 layer (reverted to R9 atomic-scatter architecture + ebias factoring):
//   K0 prep_kernel  : zero agg/sum; split X + weights into hi/lo bf16
//   K1 ebias_kernel : edge_bias[e][h] = ef[e]@We[:,h] + be[h]
//                     (sole consumer of the 204MB ef stream -> edge kernel's
//                      L/R/V gather set stays L2-resident)
//   K2 gemm_async<256,true> : [L|R] bf16 + V fp32 = X @ [Wl|Wr|Wv] + bias
//   K3 edge_kernel  : one pass, edge order: score from L/R + ebias -> exp ->
//                     red.global scatter of ex*V (unnormalized)
//   K4 normalize    : agg/sum -> hi/lo bf16
//   K5 gemm_async<128,false> : out = norm_agg @ Wo + bo
// ---------------------------------------------------------------------------

#define N_MAX 50048
#define E_MAX 800256
#define IN_F  256

__device__ __align__(16) float g_agg [(size_t)N_MAX * 128];
__device__ __align__(16) float g_sum [(size_t)N_MAX * 8];

// per-edge bias scores (pre-exp): ef@We + be
__device__ __align__(16) float g_ebias[(size_t)E_MAX * 8];

// edge-pass operands (written by proj GEMM epilogue)
__device__ __align__(16) __nv_bfloat16 g_edgeLR[(size_t)N_MAX * 256]; // [n][L|R]
__device__ __align__(16) float         g_valf  [(size_t)N_MAX * 128]; // V fp32

// bf16-split GEMM operands
__device__ __align__(16) __nv_bfloat16 g_Xhi[(size_t)N_MAX * 256];
__device__ __align__(16) __nv_bfloat16 g_Xlo[(size_t)N_MAX * 256];
__device__ __align__(16) __nv_bfloat16 g_Ahi_o[(size_t)N_MAX * 128];
__device__ __align__(16) __nv_bfloat16 g_Alo_o[(size_t)N_MAX * 128];
// transposed weights [band][n][k] (B[n][k] = W[k][n])
__device__ __align__(16) __nv_bfloat16 g_Bhi_p[3 * 128 * 256];
__device__ __align__(16) __nv_bfloat16 g_Blo_p[3 * 128 * 256];
__device__ __align__(16) __nv_bfloat16 g_Bhi_o[128 * 128];
__device__ __align__(16) __nv_bfloat16 g_Blo_o[128 * 128];
__device__ __align__(16) float g_bias_p[384];

// ------------------------------ helpers ------------------------------------
__device__ __forceinline__ uint32_t s2u(const void* p) {
    uint32_t a;
    asm("{ .reg .u64 t; cvta.to.shared.u64 t, %1; cvt.u32.u64 %0, t; }"
        : "=r"(a) : "l"(p));
    return a;
}

__device__ __forceinline__ void cpa16(uint32_t dst, const void* src) {
    asm volatile("cp.async.cg.shared.global [%0], [%1], 16;"
                 :: "r"(dst), "l"(src));
}

__device__ __forceinline__ void ldmA(uint32_t* a, uint32_t addr) {
    asm volatile("ldmatrix.sync.aligned.m8n8.x4.shared.b16 {%0,%1,%2,%3}, [%4];"
                 : "=r"(a[0]), "=r"(a[1]), "=r"(a[2]), "=r"(a[3]) : "r"(addr));
}

__device__ __forceinline__ void mma16816(float* c, const uint32_t* a,
                                         uint32_t b0, uint32_t b1) {
    asm volatile(
        "mma.sync.aligned.m16n8k16.row.col.f32.bf16.bf16.f32 "
        "{%0,%1,%2,%3},{%4,%5,%6,%7},{%8,%9},{%0,%1,%2,%3};"
        : "+f"(c[0]), "+f"(c[1]), "+f"(c[2]), "+f"(c[3])
        : "r"(a[0]), "r"(a[1]), "r"(a[2]), "r"(a[3]), "r"(b0), "r"(b1));
}

__device__ __forceinline__ float4 ldg_stream4(const float4* p) {
    return __ldcs(p);
}

// pack 2 floats -> hi bf16x2 (returned) + lo bf16x2 (out param)
__device__ __forceinline__ uint32_t pack2(float x, float y, uint32_t& lo) {
    __nv_bfloat16 hx = __float2bfloat16_rn(x);
    __nv_bfloat16 hy = __float2bfloat16_rn(y);
    __nv_bfloat16 lx = __float2bfloat16_rn(x - __bfloat162float(hx));
    __nv_bfloat16 ly = __float2bfloat16_rn(y - __bfloat162float(hy));
    lo = (uint32_t)__bfloat16_as_ushort(lx) | ((uint32_t)__bfloat16_as_ushort(ly) << 16);
    return (uint32_t)__bfloat16_as_ushort(hx) | ((uint32_t)__bfloat16_as_ushort(hy) << 16);
}

// ------------------------------- K0: prep ----------------------------------
__global__ void __launch_bounds__(256) prep_kernel(
    const float* __restrict__ X,
    const float* __restrict__ Wl, const float* __restrict__ bl,
    const float* __restrict__ Wr, const float* __restrict__ br,
    const float* __restrict__ Wv, const float* __restrict__ bv,
    const float* __restrict__ Wo, int n_nodes)
{
    int idx0 = blockIdx.x * blockDim.x + threadIdx.x;
    int stride = gridDim.x * blockDim.x;

    float4 z = make_float4(0.f, 0.f, 0.f, 0.f);
    int nAgg4 = n_nodes * 32;
    for (int i = idx0; i < nAgg4; i += stride)
        reinterpret_cast<float4*>(g_agg)[i] = z;
    for (int i = idx0; i < n_nodes * 8; i += stride)
        g_sum[i] = 0.f;

    int nX2 = n_nodes * 128;     // float pairs
    for (int i = idx0; i < nX2; i += stride) {
        float2 v = reinterpret_cast<const float2*>(X)[i];
        uint32_t lo;
        uint32_t hi = pack2(v.x, v.y, lo);
        reinterpret_cast<uint32_t*>(g_Xhi)[i] = hi;
        reinterpret_cast<uint32_t*>(g_Xlo)[i] = lo;
    }

    for (int i = idx0; i < 3 * 128 * 256; i += stride) {
        int band = i >> 15;
        int n = (i >> 8) & 127;
        int k = i & 255;
        const float* W = band == 0 ? Wl : (band == 1 ? Wr : Wv);
        float v = W[k * 128 + n];
        __nv_bfloat16 h = __float2bfloat16_rn(v);
        g_Bhi_p[i] = h;
        g_Blo_p[i] = __float2bfloat16_rn(v - __bfloat162float(h));
    }
    for (int i = idx0; i < 128 * 128; i += stride) {
        int n = i >> 7, k = i & 127;
        float v = Wo[k * 128 + n];
        __nv_bfloat16 h = __float2bfloat16_rn(v);
        g_Bhi_o[i] = h;
        g_Blo_o[i] = __float2bfloat16_rn(v - __bfloat162float(h));
    }
    for (int i = idx0; i < 384; i += stride)
        g_bias_p[i] = i < 128 ? bl[i] : (i < 256 ? br[i - 128] : bv[i - 256]);
}

// ------------- K1: edge-bias pass (EDGE order, pure stream) ----------------
__global__ void __launch_bounds__(256) ebias_kernel(
    const float* __restrict__ ef, const float* __restrict__ We,
    const float* __restrict__ be, int E)
{
    const int tid   = threadIdx.x;
    const int lane  = tid & 31;
    const int h     = lane >> 2;
    const int chunk = lane & 3;

    float beh = be[h];
    float w[16];
#pragma unroll
    for (int j = 0; j < 16; j++)
        w[j] = We[(chunk * 16 + j) * 8 + h];

    int gw = (blockIdx.x * 256 + tid) >> 5;
    int nw = (gridDim.x * 256) >> 5;

    for (int e = gw; e < E; e += nw) {
        const float4* pe = reinterpret_cast<const float4*>(ef + (size_t)e * 64 + chunk * 16);
        float4 e0 = ldg_stream4(pe + 0);
        float4 e1 = ldg_stream4(pe + 1);
        float4 e2 = ldg_stream4(pe + 2);
        float4 e3 = ldg_stream4(pe + 3);

        float p = 0.f;
        p = fmaf(e0.x, w[0],  p); p = fmaf(e0.y, w[1],  p);
        p = fmaf(e0.z, w[2],  p); p = fmaf(e0.w, w[3],  p);
        p = fmaf(e1.x, w[4],  p); p = fmaf(e1.y, w[5],  p);
        p = fmaf(e1.z, w[6],  p); p = fmaf(e1.w, w[7],  p);
        p = fmaf(e2.x, w[8],  p); p = fmaf(e2.y, w[9],  p);
        p = fmaf(e2.z, w[10], p); p = fmaf(e2.w, w[11], p);
        p = fmaf(e3.x, w[12], p); p = fmaf(e3.y, w[13], p);
        p = fmaf(e3.z, w[14], p); p = fmaf(e3.w, w[15], p);

        p += __shfl_xor_sync(0xffffffffu, p, 1);
        p += __shfl_xor_sync(0xffffffffu, p, 2);

        if (chunk == 0)
            g_ebias[(size_t)e * 8 + h] = p + beh;
    }
}

// ---------------- K2/K5: cp.async 2-stage split-bf16 MMA GEMM --------------
static constexpr int TSTRIDE = 40;
static constexpr int TILE_B  = 128 * TSTRIDE * 2;  // 10240 B
static constexpr int STAGE_B = 4 * TILE_B;         // 40960 B
static constexpr int GEMM_SMEM = 2 * STAGE_B;      // 81920 B

template<int KT, bool PROJ>
__global__ void __launch_bounds__(256, 2) gemm_async(
    const float* __restrict__ bias_ext, float* __restrict__ out_ext, int M)
{
    constexpr int NCH = KT / 32;
    extern __shared__ char smem[];
    const uint32_t sb = s2u(smem);

    const int tid  = threadIdx.x;
    const int wid  = tid >> 5;
    const int lane = tid & 31;
    const int band = blockIdx.y;
    const int rowBase = blockIdx.x * 128;
    const int warpM = (wid & 3) * 32;
    const int warpN = (wid >> 2) * 64;
    const int g  = lane >> 2;
    const int tg = lane & 3;

    const __nv_bfloat16* Ah = PROJ ? g_Xhi : g_Ahi_o;
    const __nv_bfloat16* Al = PROJ ? g_Xlo : g_Alo_o;
    const __nv_bfloat16* Bh = PROJ ? (g_Bhi_p + (size_t)band * 128 * 256) : g_Bhi_o;
    const __nv_bfloat16* Bl = PROJ ? (g_Blo_p + (size_t)band * 128 * 256) : g_Blo_o;

    const int r0c  = tid >> 2;
    const int g2c  = tid & 3;
    const uint32_t dst0 = sb + (uint32_t)(r0c * 80 + g2c * 16);
    const size_t aoff0 = ((size_t)(rowBase + r0c) * KT) * 2 + g2c * 16;
    const size_t boff0 = ((size_t)r0c * KT) * 2 + g2c * 16;

    float acc[2][8][4];
#pragma unroll
    for (int mt = 0; mt < 2; mt++)
#pragma unroll
        for (int nt = 0; nt < 8; nt++)
#pragma unroll
            for (int j = 0; j < 4; j++) acc[mt][nt][j] = 0.f;

    const uint32_t ldmOff =
        (uint32_t)(((warpM + (lane & 7) + (lane & 8)) * TSTRIDE + ((lane >> 4) << 3)) * 2);
    const uint32_t bBase = (uint32_t)((warpN + g) * (TSTRIDE / 2) + tg);

    auto issue = [&](int c, int s) {
        const size_t kb = (size_t)(c * 32) * 2;
        const uint32_t so = (uint32_t)(s * STAGE_B);
#pragma unroll
        for (int i = 0; i < 2; i++) {
            const uint32_t d = dst0 + so + (uint32_t)(i * 64 * 80);
            const size_t ao = aoff0 + kb + (size_t)i * 64 * KT * 2;
            const size_t bo = boff0 + kb + (size_t)i * 64 * KT * 2;
            cpa16(d,              (const char*)Ah + ao);
            cpa16(d + TILE_B,     (const char*)Al + ao);
            cpa16(d + 2 * TILE_B, (const char*)Bh + bo);
            cpa16(d + 3 * TILE_B, (const char*)Bl + bo);
        }
        asm volatile("cp.async.commit_group;");
    };

    issue(0, 0);
#pragma unroll
    for (int c = 0; c < NCH; c++) {
        if (c + 1 < NCH) {
            issue(c + 1, (c + 1) & 1);
            asm volatile("cp.async.wait_group 1;");
        } else {
            asm volatile("cp.async.wait_group 0;");
        }
        __syncthreads();

        const uint32_t so = (uint32_t)((c & 1) * STAGE_B);
        const uint32_t sAhi = sb + so;
        const uint32_t sAlo = sAhi + TILE_B;
        const uint32_t* BHu = reinterpret_cast<const uint32_t*>(smem + (c & 1) * STAGE_B + 2 * TILE_B);
        const uint32_t* BLu = reinterpret_cast<const uint32_t*>(smem + (c & 1) * STAGE_B + 3 * TILE_B);

#pragma unroll
        for (int k16 = 0; k16 < 2; k16++) {
            uint32_t ah[2][4], al[2][4];
            uint32_t ko = ldmOff + (uint32_t)(k16 * 32);
            ldmA(ah[0], sAhi + ko);
            ldmA(ah[1], sAhi + ko + (uint32_t)(16 * TSTRIDE * 2));
            ldmA(al[0], sAlo + ko);
            ldmA(al[1], sAlo + ko + (uint32_t)(16 * TSTRIDE * 2));
#pragma unroll
            for (int nt = 0; nt < 8; nt++) {
                uint32_t idx = bBase + (uint32_t)(nt * 8 * (TSTRIDE / 2) + k16 * 8);
                uint32_t bh0 = BHu[idx], bh1 = BHu[idx + 4];
                uint32_t bl0 = BLu[idx], bl1 = BLu[idx + 4];
                mma16816(acc[0][nt], ah[0], bh0, bh1);
                mma16816(acc[1][nt], ah[1], bh0, bh1);
                mma16816(acc[0][nt], ah[0], bl0, bl1);
                mma16816(acc[1][nt], ah[1], bl0, bl1);
                mma16816(acc[0][nt], al[0], bh0, bh1);
                mma16816(acc[1][nt], al[1], bh0, bh1);
            }
        }
        __syncthreads();
    }

    // ---- epilogue ----
    if (PROJ) {
        if (band == 2) {
            // V -> fp32 (precision-critical after softmax shrinkage)
#pragma unroll
            for (int mt = 0; mt < 2; mt++) {
                int r0 = rowBase + warpM + mt * 16 + g;
#pragma unroll
                for (int nt = 0; nt < 8; nt++) {
                    int col = warpN + nt * 8 + tg * 2;
                    float b0 = g_bias_p[256 + col], b1 = g_bias_p[256 + col + 1];
                    if (r0 < M) {
                        float2 v = make_float2(acc[mt][nt][0] + b0, acc[mt][nt][1] + b1);
                        *reinterpret_cast<float2*>(g_valf + (size_t)r0 * 128 + col) = v;
                    }
                    if (r0 + 8 < M) {
                        float2 v = make_float2(acc[mt][nt][2] + b0, acc[mt][nt][3] + b1);
                        *reinterpret_cast<float2*>(g_valf + (size_t)(r0 + 8) * 128 + col) = v;
                    }
                }
            }
        } else {
            // L/R -> bf16 (score path, abs err ~8e-5)
#pragma unroll
            for (int mt = 0; mt < 2; mt++) {
                int r0 = rowBase + warpM + mt * 16 + g;
#pragma unroll
                for (int nt = 0; nt < 8; nt++) {
                    int col = warpN + nt * 8 + tg * 2;
                    float b0 = g_bias_p[band * 128 + col];
                    float b1 = g_bias_p[band * 128 + col + 1];
                    if (r0 < M) {
                        __nv_bfloat162 h = __floats2bfloat162_rn(acc[mt][nt][0] + b0,
                                                                 acc[mt][nt][1] + b1);
                        *reinterpret_cast<__nv_bfloat162*>(
                            g_edgeLR + (size_t)r0 * 256 + band * 128 + col) = h;
                    }
                    if (r0 + 8 < M) {
                        __nv_bfloat162 h = __floats2bfloat162_rn(acc[mt][nt][2] + b0,
                                                                 acc[mt][nt][3] + b1);
                        *reinterpret_cast<__nv_bfloat162*>(
                            g_edgeLR + (size_t)(r0 + 8) * 256 + band * 128 + col) = h;
                    }
                }
            }
        }
    } else {
#pragma unroll
        for (int mt = 0; mt < 2; mt++) {
            int r0 = rowBase + warpM + mt * 16 + g;
#pragma unroll
            for (int nt = 0; nt < 8; nt++) {
                int col = warpN + nt * 8 + tg * 2;
                float b0 = bias_ext[col], b1 = bias_ext[col + 1];
                if (r0 < M) {
                    float2 v = make_float2(acc[mt][nt][0] + b0, acc[mt][nt][1] + b1);
                    *reinterpret_cast<float2*>(out_ext + (size_t)r0 * 128 + col) = v;
                }
                if (r0 + 8 < M) {
                    float2 v = make_float2(acc[mt][nt][2] + b0, acc[mt][nt][3] + b1);
                    *reinterpret_cast<float2*>(out_ext + (size_t)(r0 + 8) * 128 + col) = v;
                }
            }
        }
    }
}

// ------------------------------ K3: edge pass ------------------------------
// Warp per edge, EDGE order (R9 architecture). L/R bf16 + V fp32 gathers all
// L2-resident now that ef no longer streams through this kernel; edge bias is
// one 4B broadcast load from g_ebias.
__global__ void __launch_bounds__(256) edge_kernel(
    const int* __restrict__ ei, const float* __restrict__ av, int E)
{
    const int tid  = threadIdx.x;
    const int lane = tid & 31;
    const int h    = lane >> 2;
    const int i0   = lane << 2;

    float4 A4 = *reinterpret_cast<const float4*>(av + i0);

    int gw = (blockIdx.x * 256 + tid) >> 5;
    int nw = (gridDim.x * 256) >> 5;

    int sN = 0, tN = 0;
    if (gw < E) { sN = __ldg(ei + gw); tN = __ldg(ei + E + gw); }

    for (int e = gw; e < E; e += nw) {
        int s = sN, t = tN;
        int en = e + nw;
        if (en < E) { sN = __ldg(ei + en); tN = __ldg(ei + E + en); }

        const __nv_bfloat162* Lp =
            reinterpret_cast<const __nv_bfloat162*>(g_edgeLR + (size_t)t * 256 + i0);
        const __nv_bfloat162* Rp =
            reinterpret_cast<const __nv_bfloat162*>(g_edgeLR + (size_t)s * 256 + 128 + i0);
        __nv_bfloat162 Lb0 = Lp[0], Lb1 = Lp[1];
        __nv_bfloat162 Rb0 = Rp[0], Rb1 = Rp[1];
        float4 V = *reinterpret_cast<const float4*>(g_valf + (size_t)s * 128 + i0);
        float bias_e = __ldg(g_ebias + (size_t)e * 8 + h);

        float2 L01 = __bfloat1622float2(Lb0), L23 = __bfloat1622float2(Lb1);
        float2 R01 = __bfloat1622float2(Rb0), R23 = __bfloat1622float2(Rb1);

        float cx = L01.x + R01.x; cx = cx > 0.f ? cx : 0.2f * cx;
        float cy = L01.y + R01.y; cy = cy > 0.f ? cy : 0.2f * cy;
        float cz = L23.x + R23.x; cz = cz > 0.f ? cz : 0.2f * cz;
        float cw = L23.y + R23.y; cw = cw > 0.f ? cw : 0.2f * cw;
        float p = cx * A4.x + cy * A4.y + cz * A4.z + cw * A4.w;

        p += __shfl_xor_sync(0xffffffffu, p, 1);
        p += __shfl_xor_sync(0xffffffffu, p, 2);

        float ex = __expf(p + bias_e);

        if ((lane & 3) == 0)
            atomicAdd(g_sum + (size_t)t * 8 + h, ex);

        float* ap = g_agg + (size_t)t * 128 + i0;
        asm volatile("red.global.add.v4.f32 [%0], {%1,%2,%3,%4};"
                     :: "l"(ap), "f"(ex * V.x), "f"(ex * V.y),
                        "f"(ex * V.z), "f"(ex * V.w)
                     : "memory");
    }
}

// --------------------- K4: normalize agg -> bf16 split ---------------------
__global__ void __launch_bounds__(256) normalize_kernel(int Mpad) {
    int idx = blockIdx.x * blockDim.x + threadIdx.x;
    int stride = gridDim.x * blockDim.x;
    int total = Mpad * 32;
    for (int i = idx; i < total; i += stride) {
        int n = i >> 5, g4 = i & 31;
        float4 a = *reinterpret_cast<const float4*>(g_agg + (size_t)n * 128 + g4 * 4);
        float inv = 1.f / (g_sum[(size_t)n * 8 + (g4 >> 2)] + 1e-10f);
        a.x *= inv; a.y *= inv; a.z *= inv; a.w *= inv;
        uint2 hi, lo;
        hi.x = pack2(a.x, a.y, lo.x);
        hi.y = pack2(a.z, a.w, lo.y);
        *reinterpret_cast<uint2*>(reinterpret_cast<char*>(g_Ahi_o) + (size_t)n * 256 + g4 * 8) = hi;
        *reinterpret_cast<uint2*>(reinterpret_cast<char*>(g_Alo_o) + (size_t)n * 256 + g4 * 8) = lo;
    }
}

// ------------------------------- launcher ----------------------------------
extern "C" void kernel_launch(void* const* d_in, const int* in_sizes, int n_in,
                              void* d_out, int out_size)
{
    const float* X  = (const float*)d_in[0];
    const int*   ei = (const int*)  d_in[1];
    const float* ef = (const float*)d_in[2];
    const float* Wl = (const float*)d_in[3];
    const float* bl = (const float*)d_in[4];
    const float* Wr = (const float*)d_in[5];
    const float* br = (const float*)d_in[6];
    const float* We = (const float*)d_in[7];
    const float* be = (const float*)d_in[8];
    const float* av = (const float*)d_in[9];
    const float* Wv = (const float*)d_in[10];
    const float* bv = (const float*)d_in[11];
    const float* Wo = (const float*)d_in[12];
    const float* bo = (const float*)d_in[13];

    int n_nodes = in_sizes[0] / IN_F;
    int E       = in_sizes[1] / 2;
    float* out  = (float*)d_out;
    int nBlocks = (n_nodes + 127) / 128;
    int Mpad    = nBlocks * 128;

    cudaFuncSetAttribute(gemm_async<256, true>,
                         cudaFuncAttributeMaxDynamicSharedMemorySize, GEMM_SMEM);
    cudaFuncSetAttribute(gemm_async<128, false>,
                         cudaFuncAttributeMaxDynamicSharedMemorySize, GEMM_SMEM);

    prep_kernel<<<2048, 256>>>(X, Wl, bl, Wr, br, Wv, bv, Wo, n_nodes);

    // ebias first: drains the 204MB ef stream before the gather-heavy phase
    ebias_kernel<<<8192, 256>>>(ef, We, be, E);

    dim3 g1(nBlocks, 3);
    gemm_async<256, true><<<g1, 256, GEMM_SMEM>>>(nullptr, nullptr, n_nodes);

    edge_kernel<<<8192, 256>>>(ei, av, E);

    normalize_kernel<<<1024, 256>>>(Mpad);

    gemm_async<128, false><<<dim3(nBlocks, 1), 256, GEMM_SMEM>>>(bo, out, n_nodes);
}

// round 15
// speedup vs baseline: 1.1309x; 1.0641x over previous
#include <cuda_runtime.h>
#include <cuda_bf16.h>
#include <cstdint>

// ---------------------------------------------------------------------------
// GATv2 layer (R14 architecture + precision-matched GEMM modes):
//   K0 prep_kernel  : zero agg/sum; split X + weights into hi/lo bf16
//   K1 ebias_kernel : edge_bias[e][h] = ef[e]@We[:,h] + be[h]  (sole ef user)
//   K2 gemm<256,0>  : L,R bands — plain bf16 hi*hi MMA (outputs are bf16!)
//   K3 gemm<256,1>  : V band  — split-3 (~fp32; V is precision-critical)
//   K4 edge_kernel  : edge-order score+exp -> red.global scatter
//   K5 normalize    : agg/sum -> hi/lo bf16
//   K6 gemm<128,2>  : out = norm_agg @ Wo + bo — split-3
// ---------------------------------------------------------------------------

#define N_MAX 50048
#define E_MAX 800256
#define IN_F  256

__device__ __align__(16) float g_agg [(size_t)N_MAX * 128];
__device__ __align__(16) float g_sum [(size_t)N_MAX * 8];
__device__ __align__(16) float g_ebias[(size_t)E_MAX * 8];

__device__ __align__(16) __nv_bfloat16 g_edgeLR[(size_t)N_MAX * 256]; // [n][L|R]
__device__ __align__(16) float         g_valf  [(size_t)N_MAX * 128]; // V fp32

__device__ __align__(16) __nv_bfloat16 g_Xhi[(size_t)N_MAX * 256];
__device__ __align__(16) __nv_bfloat16 g_Xlo[(size_t)N_MAX * 256];
__device__ __align__(16) __nv_bfloat16 g_Ahi_o[(size_t)N_MAX * 128];
__device__ __align__(16) __nv_bfloat16 g_Alo_o[(size_t)N_MAX * 128];
__device__ __align__(16) __nv_bfloat16 g_Bhi_p[3 * 128 * 256];
__device__ __align__(16) __nv_bfloat16 g_Blo_p[3 * 128 * 256];
__device__ __align__(16) __nv_bfloat16 g_Bhi_o[128 * 128];
__device__ __align__(16) __nv_bfloat16 g_Blo_o[128 * 128];
__device__ __align__(16) float g_bias_p[384];

// ------------------------------ helpers ------------------------------------
__device__ __forceinline__ uint32_t s2u(const void* p) {
    uint32_t a;
    asm("{ .reg .u64 t; cvta.to.shared.u64 t, %1; cvt.u32.u64 %0, t; }"
        : "=r"(a) : "l"(p));
    return a;
}

__device__ __forceinline__ void cpa16(uint32_t dst, const void* src) {
    asm volatile("cp.async.cg.shared.global [%0], [%1], 16;"
                 :: "r"(dst), "l"(src));
}

__device__ __forceinline__ void ldmA(uint32_t* a, uint32_t addr) {
    asm volatile("ldmatrix.sync.aligned.m8n8.x4.shared.b16 {%0,%1,%2,%3}, [%4];"
                 : "=r"(a[0]), "=r"(a[1]), "=r"(a[2]), "=r"(a[3]) : "r"(addr));
}

__device__ __forceinline__ void mma16816(float* c, const uint32_t* a,
                                         uint32_t b0, uint32_t b1) {
    asm volatile(
        "mma.sync.aligned.m16n8k16.row.col.f32.bf16.bf16.f32 "
        "{%0,%1,%2,%3},{%4,%5,%6,%7},{%8,%9},{%0,%1,%2,%3};"
        : "+f"(c[0]), "+f"(c[1]), "+f"(c[2]), "+f"(c[3])
        : "r"(a[0]), "r"(a[1]), "r"(a[2]), "r"(a[3]), "r"(b0), "r"(b1));
}

__device__ __forceinline__ float4 ldg_stream4(const float4* p) {
    return __ldcs(p);
}

__device__ __forceinline__ uint32_t pack2(float x, float y, uint32_t& lo) {
    __nv_bfloat16 hx = __float2bfloat16_rn(x);
    __nv_bfloat16 hy = __float2bfloat16_rn(y);
    __nv_bfloat16 lx = __float2bfloat16_rn(x - __bfloat162float(hx));
    __nv_bfloat16 ly = __float2bfloat16_rn(y - __bfloat162float(hy));
    lo = (uint32_t)__bfloat16_as_ushort(lx) | ((uint32_t)__bfloat16_as_ushort(ly) << 16);
    return (uint32_t)__bfloat16_as_ushort(hx) | ((uint32_t)__bfloat16_as_ushort(hy) << 16);
}

// ------------------------------- K0: prep ----------------------------------
__global__ void __launch_bounds__(256) prep_kernel(
    const float* __restrict__ X,
    const float* __restrict__ Wl, const float* __restrict__ bl,
    const float* __restrict__ Wr, const float* __restrict__ br,
    const float* __restrict__ Wv, const float* __restrict__ bv,
    const float* __restrict__ Wo, int n_nodes)
{
    int idx0 = blockIdx.x * blockDim.x + threadIdx.x;
    int stride = gridDim.x * blockDim.x;

    float4 z = make_float4(0.f, 0.f, 0.f, 0.f);
    int nAgg4 = n_nodes * 32;
    for (int i = idx0; i < nAgg4; i += stride)
        reinterpret_cast<float4*>(g_agg)[i] = z;
    for (int i = idx0; i < n_nodes * 8; i += stride)
        g_sum[i] = 0.f;

    int nX2 = n_nodes * 128;
    for (int i = idx0; i < nX2; i += stride) {
        float2 v = reinterpret_cast<const float2*>(X)[i];
        uint32_t lo;
        uint32_t hi = pack2(v.x, v.y, lo);
        reinterpret_cast<uint32_t*>(g_Xhi)[i] = hi;
        reinterpret_cast<uint32_t*>(g_Xlo)[i] = lo;
    }

    for (int i = idx0; i < 3 * 128 * 256; i += stride) {
        int band = i >> 15;
        int n = (i >> 8) & 127;
        int k = i & 255;
        const float* W = band == 0 ? Wl : (band == 1 ? Wr : Wv);
        float v = W[k * 128 + n];
        __nv_bfloat16 h = __float2bfloat16_rn(v);
        g_Bhi_p[i] = h;
        g_Blo_p[i] = __float2bfloat16_rn(v - __bfloat162float(h));
    }
    for (int i = idx0; i < 128 * 128; i += stride) {
        int n = i >> 7, k = i & 127;
        float v = Wo[k * 128 + n];
        __nv_bfloat16 h = __float2bfloat16_rn(v);
        g_Bhi_o[i] = h;
        g_Blo_o[i] = __float2bfloat16_rn(v - __bfloat162float(h));
    }
    for (int i = idx0; i < 384; i += stride)
        g_bias_p[i] = i < 128 ? bl[i] : (i < 256 ? br[i - 128] : bv[i - 256]);
}

// ------------- K1: edge-bias pass (EDGE order, pure stream) ----------------
__global__ void __launch_bounds__(256) ebias_kernel(
    const float* __restrict__ ef, const float* __restrict__ We,
    const float* __restrict__ be, int E)
{
    const int tid   = threadIdx.x;
    const int lane  = tid & 31;
    const int h     = lane >> 2;
    const int chunk = lane & 3;

    float beh = be[h];
    float w[16];
#pragma unroll
    for (int j = 0; j < 16; j++)
        w[j] = We[(chunk * 16 + j) * 8 + h];

    int gw = (blockIdx.x * 256 + tid) >> 5;
    int nw = (gridDim.x * 256) >> 5;

    for (int e = gw; e < E; e += nw) {
        const float4* pe = reinterpret_cast<const float4*>(ef + (size_t)e * 64 + chunk * 16);
        float4 e0 = ldg_stream4(pe + 0);
        float4 e1 = ldg_stream4(pe + 1);
        float4 e2 = ldg_stream4(pe + 2);
        float4 e3 = ldg_stream4(pe + 3);

        float p = 0.f;
        p = fmaf(e0.x, w[0],  p); p = fmaf(e0.y, w[1],  p);
        p = fmaf(e0.z, w[2],  p); p = fmaf(e0.w, w[3],  p);
        p = fmaf(e1.x, w[4],  p); p = fmaf(e1.y, w[5],  p);
        p = fmaf(e1.z, w[6],  p); p = fmaf(e1.w, w[7],  p);
        p = fmaf(e2.x, w[8],  p); p = fmaf(e2.y, w[9],  p);
        p = fmaf(e2.z, w[10], p); p = fmaf(e2.w, w[11], p);
        p = fmaf(e3.x, w[12], p); p = fmaf(e3.y, w[13], p);
        p = fmaf(e3.z, w[14], p); p = fmaf(e3.w, w[15], p);

        p += __shfl_xor_sync(0xffffffffu, p, 1);
        p += __shfl_xor_sync(0xffffffffu, p, 2);

        if (chunk == 0)
            g_ebias[(size_t)e * 8 + h] = p + beh;
    }
}

// -------------- K2/K3/K6: cp.async 2-stage MMA GEMM (3 modes) --------------
// MODE 0: proj L/R bands — hi*hi only (bf16 result precision), 2 tiles/stage
// MODE 1: proj V band   — split-3 (~fp32), 4 tiles/stage
// MODE 2: out GEMM      — split-3 (~fp32), 4 tiles/stage
static constexpr int TSTRIDE = 40;
static constexpr int TILE_B  = 128 * TSTRIDE * 2;  // 10240 B

template<int KT, int MODE>
__global__ void __launch_bounds__(256, 2) gemm_async(
    const float* __restrict__ bias_ext, float* __restrict__ out_ext, int M)
{
    constexpr bool SPLIT = (MODE != 0);
    constexpr int NTILES = SPLIT ? 4 : 2;
    constexpr int STAGE_B = NTILES * TILE_B;
    constexpr int NCH = KT / 32;

    extern __shared__ char smem[];
    const uint32_t sb = s2u(smem);

    const int tid  = threadIdx.x;
    const int lane = tid & 31;
    const int wid  = tid >> 5;
    const int band = (MODE == 0) ? blockIdx.y : 2;
    const int rowBase = blockIdx.x * 128;
    const int warpM = (wid & 3) * 32;
    const int warpN = (wid >> 2) * 64;
    const int g  = lane >> 2;
    const int tg = lane & 3;

    const __nv_bfloat16* Ah = (MODE == 2) ? g_Ahi_o : g_Xhi;
    const __nv_bfloat16* Al = (MODE == 2) ? g_Alo_o : g_Xlo;
    const __nv_bfloat16* Bh = (MODE == 2) ? g_Bhi_o : (g_Bhi_p + (size_t)band * 128 * 256);
    const __nv_bfloat16* Bl = (MODE == 2) ? g_Blo_o : (g_Blo_p + (size_t)band * 128 * 256);

    const int r0c  = tid >> 2;
    const int g2c  = tid & 3;
    const uint32_t dst0 = sb + (uint32_t)(r0c * 80 + g2c * 16);
    const size_t aoff0 = ((size_t)(rowBase + r0c) * KT) * 2 + g2c * 16;
    const size_t boff0 = ((size_t)r0c * KT) * 2 + g2c * 16;

    float acc[2][8][4];
#pragma unroll
    for (int mt = 0; mt < 2; mt++)
#pragma unroll
        for (int nt = 0; nt < 8; nt++)
#pragma unroll
            for (int j = 0; j < 4; j++) acc[mt][nt][j] = 0.f;

    const uint32_t ldmOff =
        (uint32_t)(((warpM + (lane & 7) + (lane & 8)) * TSTRIDE + ((lane >> 4) << 3)) * 2);
    const uint32_t bBase = (uint32_t)((warpN + g) * (TSTRIDE / 2) + tg);

    // tile offsets within a stage: [Ah | (Al) | Bh | (Bl)]
    constexpr uint32_t OFF_AH = 0;
    constexpr uint32_t OFF_AL = SPLIT ? TILE_B : 0;
    constexpr uint32_t OFF_BH = SPLIT ? 2 * TILE_B : TILE_B;
    constexpr uint32_t OFF_BL = SPLIT ? 3 * TILE_B : 0;

    auto issue = [&](int c, int s) {
        const size_t kb = (size_t)(c * 32) * 2;
        const uint32_t so = (uint32_t)(s * STAGE_B);
#pragma unroll
        for (int i = 0; i < 2; i++) {
            const uint32_t d = dst0 + so + (uint32_t)(i * 64 * 80);
            const size_t ao = aoff0 + kb + (size_t)i * 64 * KT * 2;
            const size_t bo = boff0 + kb + (size_t)i * 64 * KT * 2;
            cpa16(d + OFF_AH, (const char*)Ah + ao);
            cpa16(d + OFF_BH, (const char*)Bh + bo);
            if (SPLIT) {
                cpa16(d + OFF_AL, (const char*)Al + ao);
                cpa16(d + OFF_BL, (const char*)Bl + bo);
            }
        }
        asm volatile("cp.async.commit_group;");
    };

    issue(0, 0);
#pragma unroll
    for (int c = 0; c < NCH; c++) {
        if (c + 1 < NCH) {
            issue(c + 1, (c + 1) & 1);
            asm volatile("cp.async.wait_group 1;");
        } else {
            asm volatile("cp.async.wait_group 0;");
        }
        __syncthreads();

        const uint32_t so = (uint32_t)((c & 1) * STAGE_B);
        const uint32_t sAhi = sb + so + OFF_AH;
        const uint32_t sAlo = sb + so + OFF_AL;
        const uint32_t* BHu =
            reinterpret_cast<const uint32_t*>(smem + (c & 1) * STAGE_B + OFF_BH);
        const uint32_t* BLu =
            reinterpret_cast<const uint32_t*>(smem + (c & 1) * STAGE_B + OFF_BL);

#pragma unroll
        for (int k16 = 0; k16 < 2; k16++) {
            uint32_t ah[2][4], al[2][4];
            uint32_t ko = ldmOff + (uint32_t)(k16 * 32);
            ldmA(ah[0], sAhi + ko);
            ldmA(ah[1], sAhi + ko + (uint32_t)(16 * TSTRIDE * 2));
            if (SPLIT) {
                ldmA(al[0], sAlo + ko);
                ldmA(al[1], sAlo + ko + (uint32_t)(16 * TSTRIDE * 2));
            }
#pragma unroll
            for (int nt = 0; nt < 8; nt++) {
                uint32_t idx = bBase + (uint32_t)(nt * 8 * (TSTRIDE / 2) + k16 * 8);
                uint32_t bh0 = BHu[idx], bh1 = BHu[idx + 4];
                mma16816(acc[0][nt], ah[0], bh0, bh1);
                mma16816(acc[1][nt], ah[1], bh0, bh1);
                if (SPLIT) {
                    uint32_t bl0 = BLu[idx], bl1 = BLu[idx + 4];
                    mma16816(acc[0][nt], ah[0], bl0, bl1);
                    mma16816(acc[1][nt], ah[1], bl0, bl1);
                    mma16816(acc[0][nt], al[0], bh0, bh1);
                    mma16816(acc[1][nt], al[1], bh0, bh1);
                }
            }
        }
        __syncthreads();
    }

    // ---- epilogue ----
    if (MODE == 0) {
        // L/R -> bf16 (score path)
#pragma unroll
        for (int mt = 0; mt < 2; mt++) {
            int r0 = rowBase + warpM + mt * 16 + g;
#pragma unroll
            for (int nt = 0; nt < 8; nt++) {
                int col = warpN + nt * 8 + tg * 2;
                float b0 = g_bias_p[band * 128 + col];
                float b1 = g_bias_p[band * 128 + col + 1];
                if (r0 < M) {
                    __nv_bfloat162 h = __floats2bfloat162_rn(acc[mt][nt][0] + b0,
                                                             acc[mt][nt][1] + b1);
                    *reinterpret_cast<__nv_bfloat162*>(
                        g_edgeLR + (size_t)r0 * 256 + band * 128 + col) = h;
                }
                if (r0 + 8 < M) {
                    __nv_bfloat162 h = __floats2bfloat162_rn(acc[mt][nt][2] + b0,
                                                             acc[mt][nt][3] + b1);
                    *reinterpret_cast<__nv_bfloat162*>(
                        g_edgeLR + (size_t)(r0 + 8) * 256 + band * 128 + col) = h;
                }
            }
        }
    } else if (MODE == 1) {
        // V -> fp32 (precision-critical after softmax shrinkage)
#pragma unroll
        for (int mt = 0; mt < 2; mt++) {
            int r0 = rowBase + warpM + mt * 16 + g;
#pragma unroll
            for (int nt = 0; nt < 8; nt++) {
                int col = warpN + nt * 8 + tg * 2;
                float b0 = g_bias_p[256 + col], b1 = g_bias_p[256 + col + 1];
                if (r0 < M) {
                    float2 v = make_float2(acc[mt][nt][0] + b0, acc[mt][nt][1] + b1);
                    *reinterpret_cast<float2*>(g_valf + (size_t)r0 * 128 + col) = v;
                }
                if (r0 + 8 < M) {
                    float2 v = make_float2(acc[mt][nt][2] + b0, acc[mt][nt][3] + b1);
                    *reinterpret_cast<float2*>(g_valf + (size_t)(r0 + 8) * 128 + col) = v;
                }
            }
        }
    } else {
#pragma unroll
        for (int mt = 0; mt < 2; mt++) {
            int r0 = rowBase + warpM + mt * 16 + g;
#pragma unroll
            for (int nt = 0; nt < 8; nt++) {
                int col = warpN + nt * 8 + tg * 2;
                float b0 = bias_ext[col], b1 = bias_ext[col + 1];
                if (r0 < M) {
                    float2 v = make_float2(acc[mt][nt][0] + b0, acc[mt][nt][1] + b1);
                    *reinterpret_cast<float2*>(out_ext + (size_t)r0 * 128 + col) = v;
                }
                if (r0 + 8 < M) {
                    float2 v = make_float2(acc[mt][nt][2] + b0, acc[mt][nt][3] + b1);
                    *reinterpret_cast<float2*>(out_ext + (size_t)(r0 + 8) * 128 + col) = v;
                }
            }
        }
    }
}

static constexpr int SMEM_SPLIT = 2 * 4 * TILE_B;   // 81920
static constexpr int SMEM_FAST  = 2 * 2 * TILE_B;   // 40960

// ------------------------------ K4: edge pass ------------------------------
__global__ void __launch_bounds__(256) edge_kernel(
    const int* __restrict__ ei, const float* __restrict__ av, int E)
{
    const int tid  = threadIdx.x;
    const int lane = tid & 31;
    const int h    = lane >> 2;
    const int i0   = lane << 2;

    float4 A4 = *reinterpret_cast<const float4*>(av + i0);

    int gw = (blockIdx.x * 256 + tid) >> 5;
    int nw = (gridDim.x * 256) >> 5;

    int sN = 0, tN = 0;
    if (gw < E) { sN = __ldg(ei + gw); tN = __ldg(ei + E + gw); }

    for (int e = gw; e < E; e += nw) {
        int s = sN, t = tN;
        int en = e + nw;
        if (en < E) { sN = __ldg(ei + en); tN = __ldg(ei + E + en); }

        const __nv_bfloat162* Lp =
            reinterpret_cast<const __nv_bfloat162*>(g_edgeLR + (size_t)t * 256 + i0);
        const __nv_bfloat162* Rp =
            reinterpret_cast<const __nv_bfloat162*>(g_edgeLR + (size_t)s * 256 + 128 + i0);
        __nv_bfloat162 Lb0 = Lp[0], Lb1 = Lp[1];
        __nv_bfloat162 Rb0 = Rp[0], Rb1 = Rp[1];
        float4 V = *reinterpret_cast<const float4*>(g_valf + (size_t)s * 128 + i0);
        float bias_e = __ldg(g_ebias + (size_t)e * 8 + h);

        float2 L01 = __bfloat1622float2(Lb0), L23 = __bfloat1622float2(Lb1);
        float2 R01 = __bfloat1622float2(Rb0), R23 = __bfloat1622float2(Rb1);

        float cx = L01.x + R01.x; cx = cx > 0.f ? cx : 0.2f * cx;
        float cy = L01.y + R01.y; cy = cy > 0.f ? cy : 0.2f * cy;
        float cz = L23.x + R23.x; cz = cz > 0.f ? cz : 0.2f * cz;
        float cw = L23.y + R23.y; cw = cw > 0.f ? cw : 0.2f * cw;
        float p = cx * A4.x + cy * A4.y + cz * A4.z + cw * A4.w;

        p += __shfl_xor_sync(0xffffffffu, p, 1);
        p += __shfl_xor_sync(0xffffffffu, p, 2);

        float ex = __expf(p + bias_e);

        if ((lane & 3) == 0)
            atomicAdd(g_sum + (size_t)t * 8 + h, ex);

        float* ap = g_agg + (size_t)t * 128 + i0;
        asm volatile("red.global.add.v4.f32 [%0], {%1,%2,%3,%4};"
                     :: "l"(ap), "f"(ex * V.x), "f"(ex * V.y),
                        "f"(ex * V.z), "f"(ex * V.w)
                     : "memory");
    }
}

// --------------------- K5: normalize agg -> bf16 split ---------------------
__global__ void __launch_bounds__(256) normalize_kernel(int Mpad) {
    int idx = blockIdx.x * blockDim.x + threadIdx.x;
    int stride = gridDim.x * blockDim.x;
    int total = Mpad * 32;
    for (int i = idx; i < total; i += stride) {
        int n = i >> 5, g4 = i & 31;
        float4 a = *reinterpret_cast<const float4*>(g_agg + (size_t)n * 128 + g4 * 4);
        float inv = 1.f / (g_sum[(size_t)n * 8 + (g4 >> 2)] + 1e-10f);
        a.x *= inv; a.y *= inv; a.z *= inv; a.w *= inv;
        uint2 hi, lo;
        hi.x = pack2(a.x, a.y, lo.x);
        hi.y = pack2(a.z, a.w, lo.y);
        *reinterpret_cast<uint2*>(reinterpret_cast<char*>(g_Ahi_o) + (size_t)n * 256 + g4 * 8) = hi;
        *reinterpret_cast<uint2*>(reinterpret_cast<char*>(g_Alo_o) + (size_t)n * 256 + g4 * 8) = lo;
    }
}

// ------------------------------- launcher ----------------------------------
extern "C" void kernel_launch(void* const* d_in, const int* in_sizes, int n_in,
                              void* d_out, int out_size)
{
    const float* X  = (const float*)d_in[0];
    const int*   ei = (const int*)  d_in[1];
    const float* ef = (const float*)d_in[2];
    const float* Wl = (const float*)d_in[3];
    const float* bl = (const float*)d_in[4];
    const float* Wr = (const float*)d_in[5];
    const float* br = (const float*)d_in[6];
    const float* We = (const float*)d_in[7];
    const float* be = (const float*)d_in[8];
    const float* av = (const float*)d_in[9];
    const float* Wv = (const float*)d_in[10];
    const float* bv = (const float*)d_in[11];
    const float* Wo = (const float*)d_in[12];
    const float* bo = (const float*)d_in[13];

    int n_nodes = in_sizes[0] / IN_F;
    int E       = in_sizes[1] / 2;
    float* out  = (float*)d_out;
    int nBlocks = (n_nodes + 127) / 128;
    int Mpad    = nBlocks * 128;

    cudaFuncSetAttribute(gemm_async<256, 0>,
                         cudaFuncAttributeMaxDynamicSharedMemorySize, SMEM_FAST);
    cudaFuncSetAttribute(gemm_async<256, 1>,
                         cudaFuncAttributeMaxDynamicSharedMemorySize, SMEM_SPLIT);
    cudaFuncSetAttribute(gemm_async<128, 2>,
                         cudaFuncAttributeMaxDynamicSharedMemorySize, SMEM_SPLIT);

    prep_kernel<<<2048, 256>>>(X, Wl, bl, Wr, br, Wv, bv, Wo, n_nodes);

    ebias_kernel<<<8192, 256>>>(ef, We, be, E);

    gemm_async<256, 0><<<dim3(nBlocks, 2), 256, SMEM_FAST>>>(nullptr, nullptr, n_nodes);
    gemm_async<256, 1><<<dim3(nBlocks, 1), 256, SMEM_SPLIT>>>(nullptr, nullptr, n_nodes);

    edge_kernel<<<8192, 256>>>(ei, av, E);

    normalize_kernel<<<1024, 256>>>(Mpad);

    gemm_async<128, 2><<<dim3(nBlocks, 1), 256, SMEM_SPLIT>>>(bo, out, n_nodes);
}

// round 17
// speedup vs baseline: 1.2457x; 1.1015x over previous
#include <cuda_runtime.h>
#include <cuda_bf16.h>
#include <cstdint>

// ---------------------------------------------------------------------------
// GATv2 layer (fused edge kernel + precision-matched GEMM modes):
//   K0 prep_kernel  : zero agg/sum; split X + weights into hi/lo bf16
//   K1 gemm<256,0>  : L,R bands — plain bf16 hi*hi MMA (outputs are bf16)
//   K2 gemm<256,1>  : V band  — split-3 (~fp32; V is precision-critical)
//   K3 edge_kernel  : FUSED single pass (R9 architecture): score from
//                     L/R gathers + streamed ef@We, exp, red.global scatter
//   K4 normalize    : agg/sum -> hi/lo bf16
//   K5 gemm<128,2>  : out = norm_agg @ Wo + bo — split-3
// ---------------------------------------------------------------------------

#define N_MAX 50048
#define IN_F  256

__device__ __align__(16) float g_agg [(size_t)N_MAX * 128];
__device__ __align__(16) float g_sum [(size_t)N_MAX * 8];

__device__ __align__(16) __nv_bfloat16 g_edgeLR[(size_t)N_MAX * 256]; // [n][L|R]
__device__ __align__(16) float         g_valf  [(size_t)N_MAX * 128]; // V fp32

__device__ __align__(16) __nv_bfloat16 g_Xhi[(size_t)N_MAX * 256];
__device__ __align__(16) __nv_bfloat16 g_Xlo[(size_t)N_MAX * 256];
__device__ __align__(16) __nv_bfloat16 g_Ahi_o[(size_t)N_MAX * 128];
__device__ __align__(16) __nv_bfloat16 g_Alo_o[(size_t)N_MAX * 128];
__device__ __align__(16) __nv_bfloat16 g_Bhi_p[3 * 128 * 256];
__device__ __align__(16) __nv_bfloat16 g_Blo_p[3 * 128 * 256];
__device__ __align__(16) __nv_bfloat16 g_Bhi_o[128 * 128];
__device__ __align__(16) __nv_bfloat16 g_Blo_o[128 * 128];
__device__ __align__(16) float g_bias_p[384];

// ------------------------------ helpers ------------------------------------
__device__ __forceinline__ uint32_t s2u(const void* p) {
    uint32_t a;
    asm("{ .reg .u64 t; cvta.to.shared.u64 t, %1; cvt.u32.u64 %0, t; }"
        : "=r"(a) : "l"(p));
    return a;
}

__device__ __forceinline__ void cpa16(uint32_t dst, const void* src) {
    asm volatile("cp.async.cg.shared.global [%0], [%1], 16;"
                 :: "r"(dst), "l"(src));
}

__device__ __forceinline__ void ldmA(uint32_t* a, uint32_t addr) {
    asm volatile("ldmatrix.sync.aligned.m8n8.x4.shared.b16 {%0,%1,%2,%3}, [%4];"
                 : "=r"(a[0]), "=r"(a[1]), "=r"(a[2]), "=r"(a[3]) : "r"(addr));
}

__device__ __forceinline__ void mma16816(float* c, const uint32_t* a,
                                         uint32_t b0, uint32_t b1) {
    asm volatile(
        "mma.sync.aligned.m16n8k16.row.col.f32.bf16.bf16.f32 "
        "{%0,%1,%2,%3},{%4,%5,%6,%7},{%8,%9},{%0,%1,%2,%3};"
        : "+f"(c[0]), "+f"(c[1]), "+f"(c[2]), "+f"(c[3])
        : "r"(a[0]), "r"(a[1]), "r"(a[2]), "r"(a[3]), "r"(b0), "r"(b1));
}

__device__ __forceinline__ float4 ldg_stream4(const float4* p) {
    return __ldcs(p);
}

__device__ __forceinline__ uint32_t pack2(float x, float y, uint32_t& lo) {
    __nv_bfloat16 hx = __float2bfloat16_rn(x);
    __nv_bfloat16 hy = __float2bfloat16_rn(y);
    __nv_bfloat16 lx = __float2bfloat16_rn(x - __bfloat162float(hx));
    __nv_bfloat16 ly = __float2bfloat16_rn(y - __bfloat162float(hy));
    lo = (uint32_t)__bfloat16_as_ushort(lx) | ((uint32_t)__bfloat16_as_ushort(ly) << 16);
    return (uint32_t)__bfloat16_as_ushort(hx) | ((uint32_t)__bfloat16_as_ushort(hy) << 16);
}

// ------------------------------- K0: prep ----------------------------------
__global__ void __launch_bounds__(256) prep_kernel(
    const float* __restrict__ X,
    const float* __restrict__ Wl, const float* __restrict__ bl,
    const float* __restrict__ Wr, const float* __restrict__ br,
    const float* __restrict__ Wv, const float* __restrict__ bv,
    const float* __restrict__ Wo, int n_nodes)
{
    int idx0 = blockIdx.x * blockDim.x + threadIdx.x;
    int stride = gridDim.x * blockDim.x;

    float4 z = make_float4(0.f, 0.f, 0.f, 0.f);
    int nAgg4 = n_nodes * 32;
    for (int i = idx0; i < nAgg4; i += stride)
        reinterpret_cast<float4*>(g_agg)[i] = z;
    for (int i = idx0; i < n_nodes * 8; i += stride)
        g_sum[i] = 0.f;

    int nX2 = n_nodes * 128;
    for (int i = idx0; i < nX2; i += stride) {
        float2 v = reinterpret_cast<const float2*>(X)[i];
        uint32_t lo;
        uint32_t hi = pack2(v.x, v.y, lo);
        reinterpret_cast<uint32_t*>(g_Xhi)[i] = hi;
        reinterpret_cast<uint32_t*>(g_Xlo)[i] = lo;
    }

    for (int i = idx0; i < 3 * 128 * 256; i += stride) {
        int band = i >> 15;
        int n = (i >> 8) & 127;
        int k = i & 255;
        const float* W = band == 0 ? Wl : (band == 1 ? Wr : Wv);
        float v = W[k * 128 + n];
        __nv_bfloat16 h = __float2bfloat16_rn(v);
        g_Bhi_p[i] = h;
        g_Blo_p[i] = __float2bfloat16_rn(v - __bfloat162float(h));
    }
    for (int i = idx0; i < 128 * 128; i += stride) {
        int n = i >> 7, k = i & 127;
        float v = Wo[k * 128 + n];
        __nv_bfloat16 h = __float2bfloat16_rn(v);
        g_Bhi_o[i] = h;
        g_Blo_o[i] = __float2bfloat16_rn(v - __bfloat162float(h));
    }
    for (int i = idx0; i < 384; i += stride)
        g_bias_p[i] = i < 128 ? bl[i] : (i < 256 ? br[i - 128] : bv[i - 256]);
}

// -------------- K1/K2/K5: cp.async 2-stage MMA GEMM (3 modes) --------------
// MODE 0: proj L/R bands — hi*hi only (bf16 result precision), 2 tiles/stage
// MODE 1: proj V band   — split-3 (~fp32), 4 tiles/stage
// MODE 2: out GEMM      — split-3 (~fp32), 4 tiles/stage
static constexpr int TSTRIDE = 40;
static constexpr int TILE_B  = 128 * TSTRIDE * 2;  // 10240 B

template<int KT, int MODE>
__global__ void __launch_bounds__(256, 2) gemm_async(
    const float* __restrict__ bias_ext, float* __restrict__ out_ext, int M)
{
    constexpr bool SPLIT = (MODE != 0);
    constexpr int NTILES = SPLIT ? 4 : 2;
    constexpr int STAGE_B = NTILES * TILE_B;
    constexpr int NCH = KT / 32;

    extern __shared__ char smem[];
    const uint32_t sb = s2u(smem);

    const int tid  = threadIdx.x;
    const int lane = tid & 31;
    const int wid  = tid >> 5;
    const int band = (MODE == 0) ? blockIdx.y : 2;
    const int rowBase = blockIdx.x * 128;
    const int warpM = (wid & 3) * 32;
    const int warpN = (wid >> 2) * 64;
    const int g  = lane >> 2;
    const int tg = lane & 3;

    const __nv_bfloat16* Ah = (MODE == 2) ? g_Ahi_o : g_Xhi;
    const __nv_bfloat16* Al = (MODE == 2) ? g_Alo_o : g_Xlo;
    const __nv_bfloat16* Bh = (MODE == 2) ? g_Bhi_o : (g_Bhi_p + (size_t)band * 128 * 256);
    const __nv_bfloat16* Bl = (MODE == 2) ? g_Blo_o : (g_Blo_p + (size_t)band * 128 * 256);

    const int r0c  = tid >> 2;
    const int g2c  = tid & 3;
    const uint32_t dst0 = sb + (uint32_t)(r0c * 80 + g2c * 16);
    const size_t aoff0 = ((size_t)(rowBase + r0c) * KT) * 2 + g2c * 16;
    const size_t boff0 = ((size_t)r0c * KT) * 2 + g2c * 16;

    float acc[2][8][4];
#pragma unroll
    for (int mt = 0; mt < 2; mt++)
#pragma unroll
        for (int nt = 0; nt < 8; nt++)
#pragma unroll
            for (int j = 0; j < 4; j++) acc[mt][nt][j] = 0.f;

    const uint32_t ldmOff =
        (uint32_t)(((warpM + (lane & 7) + (lane & 8)) * TSTRIDE + ((lane >> 4) << 3)) * 2);
    const uint32_t bBase = (uint32_t)((warpN + g) * (TSTRIDE / 2) + tg);

    constexpr uint32_t OFF_AH = 0;
    constexpr uint32_t OFF_AL = SPLIT ? TILE_B : 0;
    constexpr uint32_t OFF_BH = SPLIT ? 2 * TILE_B : TILE_B;
    constexpr uint32_t OFF_BL = SPLIT ? 3 * TILE_B : 0;

    auto issue = [&](int c, int s) {
        const size_t kb = (size_t)(c * 32) * 2;
        const uint32_t so = (uint32_t)(s * STAGE_B);
#pragma unroll
        for (int i = 0; i < 2; i++) {
            const uint32_t d = dst0 + so + (uint32_t)(i * 64 * 80);
            const size_t ao = aoff0 + kb + (size_t)i * 64 * KT * 2;
            const size_t bo = boff0 + kb + (size_t)i * 64 * KT * 2;
            cpa16(d + OFF_AH, (const char*)Ah + ao);
            cpa16(d + OFF_BH, (const char*)Bh + bo);
            if (SPLIT) {
                cpa16(d + OFF_AL, (const char*)Al + ao);
                cpa16(d + OFF_BL, (const char*)Bl + bo);
            }
        }
        asm volatile("cp.async.commit_group;");
    };

    issue(0, 0);
#pragma unroll
    for (int c = 0; c < NCH; c++) {
        if (c + 1 < NCH) {
            issue(c + 1, (c + 1) & 1);
            asm volatile("cp.async.wait_group 1;");
        } else {
            asm volatile("cp.async.wait_group 0;");
        }
        __syncthreads();

        const uint32_t so = (uint32_t)((c & 1) * STAGE_B);
        const uint32_t sAhi = sb + so + OFF_AH;
        const uint32_t sAlo = sb + so + OFF_AL;
        const uint32_t* BHu =
            reinterpret_cast<const uint32_t*>(smem + (c & 1) * STAGE_B + OFF_BH);
        const uint32_t* BLu =
            reinterpret_cast<const uint32_t*>(smem + (c & 1) * STAGE_B + OFF_BL);

#pragma unroll
        for (int k16 = 0; k16 < 2; k16++) {
            uint32_t ah[2][4], al[2][4];
            uint32_t ko = ldmOff + (uint32_t)(k16 * 32);
            ldmA(ah[0], sAhi + ko);
            ldmA(ah[1], sAhi + ko + (uint32_t)(16 * TSTRIDE * 2));
            if (SPLIT) {
                ldmA(al[0], sAlo + ko);
                ldmA(al[1], sAlo + ko + (uint32_t)(16 * TSTRIDE * 2));
            }
#pragma unroll
            for (int nt = 0; nt < 8; nt++) {
                uint32_t idx = bBase + (uint32_t)(nt * 8 * (TSTRIDE / 2) + k16 * 8);
                uint32_t bh0 = BHu[idx], bh1 = BHu[idx + 4];
                mma16816(acc[0][nt], ah[0], bh0, bh1);
                mma16816(acc[1][nt], ah[1], bh0, bh1);
                if (SPLIT) {
                    uint32_t bl0 = BLu[idx], bl1 = BLu[idx + 4];
                    mma16816(acc[0][nt], ah[0], bl0, bl1);
                    mma16816(acc[1][nt], ah[1], bl0, bl1);
                    mma16816(acc[0][nt], al[0], bh0, bh1);
                    mma16816(acc[1][nt], al[1], bh0, bh1);
                }
            }
        }
        __syncthreads();
    }

    // ---- epilogue ----
    if (MODE == 0) {
#pragma unroll
        for (int mt = 0; mt < 2; mt++) {
            int r0 = rowBase + warpM + mt * 16 + g;
#pragma unroll
            for (int nt = 0; nt < 8; nt++) {
                int col = warpN + nt * 8 + tg * 2;
                float b0 = g_bias_p[band * 128 + col];
                float b1 = g_bias_p[band * 128 + col + 1];
                if (r0 < M) {
                    __nv_bfloat162 h = __floats2bfloat162_rn(acc[mt][nt][0] + b0,
                                                             acc[mt][nt][1] + b1);
                    *reinterpret_cast<__nv_bfloat162*>(
                        g_edgeLR + (size_t)r0 * 256 + band * 128 + col) = h;
                }
                if (r0 + 8 < M) {
                    __nv_bfloat162 h = __floats2bfloat162_rn(acc[mt][nt][2] + b0,
                                                             acc[mt][nt][3] + b1);
                    *reinterpret_cast<__nv_bfloat162*>(
                        g_edgeLR + (size_t)(r0 + 8) * 256 + band * 128 + col) = h;
                }
            }
        }
    } else if (MODE == 1) {
#pragma unroll
        for (int mt = 0; mt < 2; mt++) {
            int r0 = rowBase + warpM + mt * 16 + g;
#pragma unroll
            for (int nt = 0; nt < 8; nt++) {
                int col = warpN + nt * 8 + tg * 2;
                float b0 = g_bias_p[256 + col], b1 = g_bias_p[256 + col + 1];
                if (r0 < M) {
                    float2 v = make_float2(acc[mt][nt][0] + b0, acc[mt][nt][1] + b1);
                    *reinterpret_cast<float2*>(g_valf + (size_t)r0 * 128 + col) = v;
                }
                if (r0 + 8 < M) {
                    float2 v = make_float2(acc[mt][nt][2] + b0, acc[mt][nt][3] + b1);
                    *reinterpret_cast<float2*>(g_valf + (size_t)(r0 + 8) * 128 + col) = v;
                }
            }
        }
    } else {
#pragma unroll
        for (int mt = 0; mt < 2; mt++) {
            int r0 = rowBase + warpM + mt * 16 + g;
#pragma unroll
            for (int nt = 0; nt < 8; nt++) {
                int col = warpN + nt * 8 + tg * 2;
                float b0 = bias_ext[col], b1 = bias_ext[col + 1];
                if (r0 < M) {
                    float2 v = make_float2(acc[mt][nt][0] + b0, acc[mt][nt][1] + b1);
                    *reinterpret_cast<float2*>(out_ext + (size_t)r0 * 128 + col) = v;
                }
                if (r0 + 8 < M) {
                    float2 v = make_float2(acc[mt][nt][2] + b0, acc[mt][nt][3] + b1);
                    *reinterpret_cast<float2*>(out_ext + (size_t)(r0 + 8) * 128 + col) = v;
                }
            }
        }
    }
}

static constexpr int SMEM_SPLIT = 2 * 4 * TILE_B;   // 81920
static constexpr int SMEM_FAST  = 2 * 2 * TILE_B;   // 40960

// ------------------------- K3: FUSED edge pass -----------------------------
// R9 architecture: warp per edge, single pass. L/R bf16 + V fp32 gathers,
// ef streamed (ld.global.cs), We column hoisted to registers, next-iteration
// index prefetch. red.global scatter of unnormalized exp-weighted values.
__global__ void __launch_bounds__(256) edge_kernel(
    const int*   __restrict__ ei, const float* __restrict__ ef,
    const float* __restrict__ We, const float* __restrict__ be,
    const float* __restrict__ av, int E)
{
    const int tid   = threadIdx.x;
    const int lane  = tid & 31;
    const int h     = lane >> 2;
    const int chunk = lane & 3;
    const int i0    = lane << 2;

    float4 A4 = *reinterpret_cast<const float4*>(av + i0);
    float beh = be[h];
    float w[16];
#pragma unroll
    for (int j = 0; j < 16; j++)
        w[j] = We[(chunk * 16 + j) * 8 + h];

    int gw = (blockIdx.x * 256 + tid) >> 5;
    int nw = (gridDim.x * 256) >> 5;

    int sN = 0, tN = 0;
    if (gw < E) { sN = __ldg(ei + gw); tN = __ldg(ei + E + gw); }

    for (int e = gw; e < E; e += nw) {
        int s = sN, t = tN;
        int en = e + nw;
        if (en < E) { sN = __ldg(ei + en); tN = __ldg(ei + E + en); }

        const __nv_bfloat162* Lp =
            reinterpret_cast<const __nv_bfloat162*>(g_edgeLR + (size_t)t * 256 + i0);
        const __nv_bfloat162* Rp =
            reinterpret_cast<const __nv_bfloat162*>(g_edgeLR + (size_t)s * 256 + 128 + i0);
        __nv_bfloat162 Lb0 = Lp[0], Lb1 = Lp[1];
        __nv_bfloat162 Rb0 = Rp[0], Rb1 = Rp[1];
        float4 V = *reinterpret_cast<const float4*>(g_valf + (size_t)s * 128 + i0);
        const float4* pe = reinterpret_cast<const float4*>(ef + (size_t)e * 64 + chunk * 16);
        float4 e0 = ldg_stream4(pe + 0);
        float4 e1 = ldg_stream4(pe + 1);
        float4 e2 = ldg_stream4(pe + 2);
        float4 e3 = ldg_stream4(pe + 3);

        float2 L01 = __bfloat1622float2(Lb0), L23 = __bfloat1622float2(Lb1);
        float2 R01 = __bfloat1622float2(Rb0), R23 = __bfloat1622float2(Rb1);

        float cx = L01.x + R01.x; cx = cx > 0.f ? cx : 0.2f * cx;
        float cy = L01.y + R01.y; cy = cy > 0.f ? cy : 0.2f * cy;
        float cz = L23.x + R23.x; cz = cz > 0.f ? cz : 0.2f * cz;
        float cw = L23.y + R23.y; cw = cw > 0.f ? cw : 0.2f * cw;
        float p = cx * A4.x + cy * A4.y + cz * A4.z + cw * A4.w;

        p = fmaf(e0.x, w[0],  p); p = fmaf(e0.y, w[1],  p);
        p = fmaf(e0.z, w[2],  p); p = fmaf(e0.w, w[3],  p);
        p = fmaf(e1.x, w[4],  p); p = fmaf(e1.y, w[5],  p);
        p = fmaf(e1.z, w[6],  p); p = fmaf(e1.w, w[7],  p);
        p = fmaf(e2.x, w[8],  p); p = fmaf(e2.y, w[9],  p);
        p = fmaf(e2.z, w[10], p); p = fmaf(e2.w, w[11], p);
        p = fmaf(e3.x, w[12], p); p = fmaf(e3.y, w[13], p);
        p = fmaf(e3.z, w[14], p); p = fmaf(e3.w, w[15], p);

        p += __shfl_xor_sync(0xffffffffu, p, 1);
        p += __shfl_xor_sync(0xffffffffu, p, 2);

        float ex = __expf(p + beh);

        if (chunk == 0)
            atomicAdd(g_sum + (size_t)t * 8 + h, ex);

        float* ap = g_agg + (size_t)t * 128 + i0;
        asm volatile("red.global.add.v4.f32 [%0], {%1,%2,%3,%4};"
                     :: "l"(ap), "f"(ex * V.x), "f"(ex * V.y),
                        "f"(ex * V.z), "f"(ex * V.w)
                     : "memory");
    }
}

// --------------------- K4: normalize agg -> bf16 split ---------------------
__global__ void __launch_bounds__(256) normalize_kernel(int Mpad) {
    int idx = blockIdx.x * blockDim.x + threadIdx.x;
    int stride = gridDim.x * blockDim.x;
    int total = Mpad * 32;
    for (int i = idx; i < total; i += stride) {
        int n = i >> 5, g4 = i & 31;
        float4 a = *reinterpret_cast<const float4*>(g_agg + (size_t)n * 128 + g4 * 4);
        float inv = 1.f / (g_sum[(size_t)n * 8 + (g4 >> 2)] + 1e-10f);
        a.x *= inv; a.y *= inv; a.z *= inv; a.w *= inv;
        uint2 hi, lo;
        hi.x = pack2(a.x, a.y, lo.x);
        hi.y = pack2(a.z, a.w, lo.y);
        *reinterpret_cast<uint2*>(reinterpret_cast<char*>(g_Ahi_o) + (size_t)n * 256 + g4 * 8) = hi;
        *reinterpret_cast<uint2*>(reinterpret_cast<char*>(g_Alo_o) + (size_t)n * 256 + g4 * 8) = lo;
    }
}

// ------------------------------- launcher ----------------------------------
extern "C" void kernel_launch(void* const* d_in, const int* in_sizes, int n_in,
                              void* d_out, int out_size)
{
    const float* X  = (const float*)d_in[0];
    const int*   ei = (const int*)  d_in[1];
    const float* ef = (const float*)d_in[2];
    const float* Wl = (const float*)d_in[3];
    const float* bl = (const float*)d_in[4];
    const float* Wr = (const float*)d_in[5];
    const float* br = (const float*)d_in[6];
    const float* We = (const float*)d_in[7];
    const float* be = (const float*)d_in[8];
    const float* av = (const float*)d_in[9];
    const float* Wv = (const float*)d_in[10];
    const float* bv = (const float*)d_in[11];
    const float* Wo = (const float*)d_in[12];
    const float* bo = (const float*)d_in[13];

    int n_nodes = in_sizes[0] / IN_F;
    int E       = in_sizes[1] / 2;
    float* out  = (float*)d_out;
    int nBlocks = (n_nodes + 127) / 128;
    int Mpad    = nBlocks * 128;

    cudaFuncSetAttribute(gemm_async<256, 0>,
                         cudaFuncAttributeMaxDynamicSharedMemorySize, SMEM_FAST);
    cudaFuncSetAttribute(gemm_async<256, 1>,
                         cudaFuncAttributeMaxDynamicSharedMemorySize, SMEM_SPLIT);
    cudaFuncSetAttribute(gemm_async<128, 2>,
                         cudaFuncAttributeMaxDynamicSharedMemorySize, SMEM_SPLIT);

    prep_kernel<<<2048, 256>>>(X, Wl, bl, Wr, br, Wv, bv, Wo, n_nodes);

    gemm_async<256, 0><<<dim3(nBlocks, 2), 256, SMEM_FAST>>>(nullptr, nullptr, n_nodes);
    gemm_async<256, 1><<<dim3(nBlocks, 1), 256, SMEM_SPLIT>>>(nullptr, nullptr, n_nodes);

    edge_kernel<<<8192, 256>>>(ei, ef, We, be, av, E);

    normalize_kernel<<<1024, 256>>>(Mpad);

    gemm_async<128, 2><<<dim3(nBlocks, 1), 256, SMEM_SPLIT>>>(bo, out, n_nodes);
}